// round 13
// baseline (speedup 1.0000x reference)
#include <cuda_runtime.h>
#include <math.h>

// Problem constants (fixed shapes per reference)
#define NN   20000
#define EE   320000
#define ETOT (EE + NN)     // edges + self loops

// ---------------- scratch (device globals; no allocation allowed) ----------
__device__ float g_x0  [NN * 128];
__device__ float g_xl1 [NN * 512];
__device__ float g_xr1 [NN * 512];
__device__ float g_agg1[NN * 512];
__device__ float g_xl2 [NN * 128];
__device__ float g_xr2 [NN * 128];
// CSR scratch
__device__ int   g_deg   [NN + 1];
__device__ int   g_cursor[NN];
__device__ int   g_rowptr[NN + 1];
__device__ int   g_esrc  [ETOT];

// ---------------- tf32 helpers ----------------------------------------------
__device__ __forceinline__ unsigned f2tf(float x) {
    unsigned r;
    asm("cvt.rna.tf32.f32 %0, %1;" : "=r"(r) : "f"(x));
    return r;
}

__device__ __forceinline__ void mma_tf32(float* d, const unsigned* a, const unsigned* b) {
    asm volatile(
        "mma.sync.aligned.m16n8k8.row.col.f32.tf32.tf32.f32 "
        "{%0,%1,%2,%3}, {%4,%5,%6,%7}, {%8,%9}, {%0,%1,%2,%3};"
        : "+f"(d[0]), "+f"(d[1]), "+f"(d[2]), "+f"(d[3])
        : "r"(a[0]), "r"(a[1]), "r"(a[2]), "r"(a[3]), "r"(b[0]), "r"(b[1]));
}

// ---------------- GEMM: 64x64 tile, 3xTF32, double-buffered ------------------
// C[M,N] = act(A @ B + bias). Grid.x covers nx n-tiles for (B1,C1) and, if
// B2 != null, nx more for (B2,C2) — merges the l/r weight GEMMs (shared A).
// GATHER builds A rows on the fly: cols 0..127 = emb[id[r]], cols 128.. = feats.
// Requires N % 64 == 0, K % 16 == 0. Dynamic smem = 36864 bytes.
#define GEMM_SMEM 36864
template <bool GATHER>
__global__ void __launch_bounds__(256, 3)
k_gemm(const float* __restrict__ A,
       const float* __restrict__ B1, const float* __restrict__ B2,
       const float* __restrict__ bias,
       float* __restrict__ C1, float* __restrict__ C2,
       int M, int N, int K, int relu, int nx,
       const float* __restrict__ xp, const float* __restrict__ emb) {
    extern __shared__ float sm[];
    // per buffer: Ah[16][72] Al[16][72] Bh[16][72] Bl[16][72]
    const int STR = 72;
    const int PSZ = 16 * STR;               // 1152 floats per plane
    const int BUFSZ = 4 * PSZ;              // 4608 floats per buffer

    int tid  = threadIdx.x;                 // 256 threads = 8 warps
    int lane = tid & 31;
    int warp = tid >> 5;
    int wm = warp >> 1;                     // 0..3 : 16-row slab
    int wn = warp & 1;                      // 0..1 : 32-col slab
    int g  = lane >> 2;                     // group 0..7
    int tg = lane & 3;                      // thread-in-group 0..3

    int bxr = blockIdx.x;
    bool sel = bxr >= nx;
    const float* B = sel ? B2 : B1;
    float* C = sel ? C2 : C1;
    int bn = (sel ? bxr - nx : bxr) * 64;
    int bm = blockIdx.y * 64;

    float acc[4][4] = {};                   // [nt][c0..c3]

    // global staging roles
    int ar = tid >> 2;                      // 0..63 : A-tile row
    int ac = (tid & 3) * 4;                 // 0,4,8,12 : A k-offset (4 floats)
    int br = tid >> 4;                      // 0..15 : B k-row
    int bc = (tid & 15) * 4;                // 0..60 : B col offset (4 floats)
    bool aok = (bm + ar) < M;
    const float* Ap = GATHER ? nullptr : A + (size_t)(bm + ar) * K + ac;
    int gid = 0;
    if (GATHER && aok) gid = (int)xp[(size_t)(bm + ar) * 65];

    float av[4], bv[4];
    auto loadTile = [&](int k0) {
        if (aok) {
            if (GATHER) {
                int kc = k0 + ac;
                if (kc < 128) {
                    float4 v = *(const float4*)(emb + (size_t)gid * 128 + kc);
                    av[0] = v.x; av[1] = v.y; av[2] = v.z; av[3] = v.w;
                } else {
                    const float* p = xp + (size_t)(bm + ar) * 65 + 1 + (kc - 128);
                    av[0] = p[0]; av[1] = p[1]; av[2] = p[2]; av[3] = p[3];
                }
            } else {
                float4 v = *(const float4*)(Ap + k0);
                av[0] = v.x; av[1] = v.y; av[2] = v.z; av[3] = v.w;
            }
        } else {
            av[0] = av[1] = av[2] = av[3] = 0.f;
        }
        float4 v = *(const float4*)(B + (size_t)(k0 + br) * N + bn + bc);
        bv[0] = v.x; bv[1] = v.y; bv[2] = v.z; bv[3] = v.w;
    };

    auto stage = [&](int buf) {
        float* Ah = sm + buf * BUFSZ;
        float* Al = Ah + PSZ;
        float* Bh = Al + PSZ;
        float* Bl = Bh + PSZ;
#pragma unroll
        for (int i = 0; i < 4; i++) {
            float hi = __uint_as_float(f2tf(av[i]));
            float lo = __uint_as_float(f2tf(av[i] - hi));
            Ah[(ac + i) * STR + ar] = hi;
            Al[(ac + i) * STR + ar] = lo;
        }
#pragma unroll
        for (int i = 0; i < 4; i++) {
            float hi = __uint_as_float(f2tf(bv[i]));
            float lo = __uint_as_float(f2tf(bv[i] - hi));
            Bh[br * STR + bc + i] = hi;
            Bl[br * STR + bc + i] = lo;
        }
    };

    auto compute = [&](int buf) {
        const float* Ah = sm + buf * BUFSZ;
        const float* Al = Ah + PSZ;
        const float* Bh = Al + PSZ;
        const float* Bl = Bh + PSZ;
#pragma unroll
        for (int kc = 0; kc < 16; kc += 8) {
            int row = wm * 16 + g;
            unsigned ahf[4], alf[4];
            ahf[0] = __float_as_uint(Ah[(kc + tg) * STR + row]);
            ahf[1] = __float_as_uint(Ah[(kc + tg) * STR + row + 8]);
            ahf[2] = __float_as_uint(Ah[(kc + tg + 4) * STR + row]);
            ahf[3] = __float_as_uint(Ah[(kc + tg + 4) * STR + row + 8]);
            alf[0] = __float_as_uint(Al[(kc + tg) * STR + row]);
            alf[1] = __float_as_uint(Al[(kc + tg) * STR + row + 8]);
            alf[2] = __float_as_uint(Al[(kc + tg + 4) * STR + row]);
            alf[3] = __float_as_uint(Al[(kc + tg + 4) * STR + row + 8]);
#pragma unroll
            for (int nt = 0; nt < 4; nt++) {
                int col = wn * 32 + nt * 8 + g;
                unsigned bhf[2], blf[2];
                bhf[0] = __float_as_uint(Bh[(kc + tg) * STR + col]);
                bhf[1] = __float_as_uint(Bh[(kc + tg + 4) * STR + col]);
                blf[0] = __float_as_uint(Bl[(kc + tg) * STR + col]);
                blf[1] = __float_as_uint(Bl[(kc + tg + 4) * STR + col]);
                mma_tf32(acc[nt], ahf, bhf);   // hi*hi
                mma_tf32(acc[nt], ahf, blf);   // hi*lo
                mma_tf32(acc[nt], alf, bhf);   // lo*hi
            }
        }
    };

    int kiters = K >> 4;
    loadTile(0);
    stage(0);
    __syncthreads();
    for (int it = 0; it < kiters; ++it) {
        int buf = it & 1;
        bool have = (it + 1 < kiters);
        if (have) loadTile((it + 1) << 4);
        compute(buf);
        if (have) stage(buf ^ 1);
        __syncthreads();
    }

    // ---- epilogue ----
    int r0 = bm + wm * 16 + g;
#pragma unroll
    for (int nt = 0; nt < 4; nt++) {
        int c0 = bn + wn * 32 + nt * 8 + tg * 2;
        float v0 = acc[nt][0], v1 = acc[nt][1];
        float v2 = acc[nt][2], v3 = acc[nt][3];
        if (bias) {
            v0 += bias[c0]; v1 += bias[c0 + 1];
            v2 += bias[c0]; v3 += bias[c0 + 1];
        }
        if (relu) {
            v0 = fmaxf(v0, 0.f); v1 = fmaxf(v1, 0.f);
            v2 = fmaxf(v2, 0.f); v3 = fmaxf(v3, 0.f);
        }
        if (r0 < M)     *(float2*)(C + (size_t)r0 * N + c0)       = make_float2(v0, v1);
        if (r0 + 8 < M) *(float2*)(C + (size_t)(r0 + 8) * N + c0) = make_float2(v2, v3);
    }
}

// ---------------- CSR build --------------------------------------------------
__global__ void k_hist(const int* __restrict__ ei, int* __restrict__ deg, int ne, int nn) {
    int i = blockIdx.x * blockDim.x + threadIdx.x;
    int tot = ne + nn;
    if (i >= tot) return;
    int d = (i < ne) ? ei[ne + i] : i - ne;
    atomicAdd(&deg[d], 1);
}

// single-block warp-shuffle scan (1024 threads = 32 warps)
__global__ void k_scan(const int* __restrict__ deg, int* __restrict__ rowptr, int n) {
    __shared__ int wsum[32];
    __shared__ int carry_s;
    int t = threadIdx.x, lane = t & 31, wid = t >> 5;
    if (t == 0) carry_s = 0;
    __syncthreads();
    for (int base = 0; base < n; base += 1024) {
        int i = base + t;
        int carry = carry_s;
        int v = (i < n) ? deg[i] : 0;
        int x = v;
#pragma unroll
        for (int o = 1; o < 32; o <<= 1) {
            int y = __shfl_up_sync(0xffffffffu, x, o);
            if (lane >= o) x += y;
        }
        if (lane == 31) wsum[wid] = x;
        __syncthreads();
        if (wid == 0) {
            int s = wsum[lane];
#pragma unroll
            for (int o = 1; o < 32; o <<= 1) {
                int y = __shfl_up_sync(0xffffffffu, s, o);
                if (lane >= o) s += y;
            }
            wsum[lane] = s;
        }
        __syncthreads();
        int woff = wid ? wsum[wid - 1] : 0;
        if (i < n) rowptr[i] = carry + woff + x - v;   // exclusive
        int total = wsum[31];
        __syncthreads();
        if (t == 0) carry_s = carry + total;
        __syncthreads();
    }
    if (t == 0) rowptr[n] = carry_s;
}

__global__ void k_scatter(const int* __restrict__ ei, const int* __restrict__ rowptr,
                          int* __restrict__ cursor, int* __restrict__ esrc,
                          int ne, int nn) {
    int i = blockIdx.x * blockDim.x + threadIdx.x;
    int tot = ne + nn;
    if (i >= tot) return;
    int s, d;
    if (i < ne) { s = ei[i]; d = ei[ne + i]; } else { s = d = i - ne; }
    int pos = rowptr[d] + atomicAdd(&cursor[d], 1);
    esrc[pos] = s;
}

// ---------------- fused GATv2 edge phase (flash-style online softmax) --------
// Layer 1: 4 heads x 128 ch. Block = 128 threads (4 warps) per node.
__global__ void k_fused1(const float* __restrict__ xl, const float* __restrict__ xr,
                         const int* __restrict__ rowptr, const int* __restrict__ esrc,
                         const float* __restrict__ att, const float* __restrict__ bias,
                         float* __restrict__ out) {
    int node = blockIdx.x;
    int t = threadIdx.x, warp = t >> 5, lane = t & 31;
    int beg = rowptr[node], end = rowptr[node + 1];

    float xrv[16], attv[16];
    const float* pxr = xr + (size_t)node * 512;
#pragma unroll
    for (int i = 0; i < 16; i++) {
        int c = i * 32 + lane;
        xrv[i] = pxr[c];
        attv[i] = att[c];
    }
    float m[4] = {-INFINITY, -INFINITY, -INFINITY, -INFINITY};
    float s[4] = {0.f, 0.f, 0.f, 0.f};
    float acc[16] = {};

    for (int j = beg + warp; j < end; j += 4) {
        const float* px = xl + (size_t)esrc[j] * 512;
        float xv[16], p[4] = {0.f, 0.f, 0.f, 0.f};
#pragma unroll
        for (int i = 0; i < 16; i++) {
            xv[i] = px[i * 32 + lane];
            float v = xv[i] + xrv[i];
            v = v > 0.f ? v : 0.2f * v;
            p[i >> 2] += v * attv[i];
        }
#pragma unroll
        for (int o = 16; o; o >>= 1) {
            p[0] += __shfl_xor_sync(0xffffffffu, p[0], o);
            p[1] += __shfl_xor_sync(0xffffffffu, p[1], o);
            p[2] += __shfl_xor_sync(0xffffffffu, p[2], o);
            p[3] += __shfl_xor_sync(0xffffffffu, p[3], o);
        }
#pragma unroll
        for (int h = 0; h < 4; h++) {
            float e = p[h];
            float mn = fmaxf(m[h], e);
            float sc = __expf(m[h] - mn);       // first edge: exp(-inf)=0
            float w  = __expf(e - mn);
            s[h] = s[h] * sc + w;
            m[h] = mn;
#pragma unroll
            for (int i = 0; i < 4; i++) {
                int ii = h * 4 + i;
                acc[ii] = acc[ii] * sc + w * xv[ii];
            }
        }
    }

    __shared__ float sm[4][4], ss[4][4];
    __shared__ float sacc[4][512];
    if (lane < 4) { sm[warp][lane] = m[lane]; ss[warp][lane] = s[lane]; }
#pragma unroll
    for (int i = 0; i < 16; i++) sacc[warp][i * 32 + lane] = acc[i];
    __syncthreads();

#pragma unroll
    for (int h = 0; h < 4; h++) {
        int c = h * 128 + t;
        float M = fmaxf(fmaxf(sm[0][h], sm[1][h]), fmaxf(sm[2][h], sm[3][h]));
        float S = 0.f, A = 0.f;
#pragma unroll
        for (int w = 0; w < 4; w++) {
            float sc = __expf(sm[w][h] - M);    // empty warp: m=-inf -> 0
            S += ss[w][h] * sc;
            A += sacc[w][c] * sc;
        }
        out[(size_t)node * 512 + c] = fmaxf(A / (S + 1e-16f) + bias[c], 0.f);
    }
}

// Layer 2 (1 head x 128 ch) + fused output head: out[node,10].
__global__ void k_fused2(const float* __restrict__ xl, const float* __restrict__ xr,
                         const int* __restrict__ rowptr, const int* __restrict__ esrc,
                         const float* __restrict__ att, const float* __restrict__ bias,
                         const float* __restrict__ oW, const float* __restrict__ ob,
                         float* __restrict__ out) {
    int node = blockIdx.x;
    int t = threadIdx.x, warp = t >> 5, lane = t & 31;
    int beg = rowptr[node], end = rowptr[node + 1];

    float xrv[4], attv[4];
    const float* pxr = xr + (size_t)node * 128;
#pragma unroll
    for (int i = 0; i < 4; i++) {
        int c = i * 32 + lane;
        xrv[i] = pxr[c];
        attv[i] = att[c];
    }
    float m = -INFINITY, s = 0.f;
    float acc[4] = {};

    for (int j = beg + warp; j < end; j += 4) {
        const float* px = xl + (size_t)esrc[j] * 128;
        float xv[4], p = 0.f;
#pragma unroll
        for (int i = 0; i < 4; i++) {
            xv[i] = px[i * 32 + lane];
            float v = xv[i] + xrv[i];
            v = v > 0.f ? v : 0.2f * v;
            p += v * attv[i];
        }
#pragma unroll
        for (int o = 16; o; o >>= 1) p += __shfl_xor_sync(0xffffffffu, p, o);
        float mn = fmaxf(m, p);
        float sc = __expf(m - mn);
        float w  = __expf(p - mn);
        s = s * sc + w;
        m = mn;
#pragma unroll
        for (int i = 0; i < 4; i++) acc[i] = acc[i] * sc + w * xv[i];
    }

    __shared__ float sm[4], ss[4];
    __shared__ float sacc[4][128];
    if (!lane) { sm[warp] = m; ss[warp] = s; }
#pragma unroll
    for (int i = 0; i < 4; i++) sacc[warp][i * 32 + lane] = acc[i];
    __syncthreads();

    float M = fmaxf(fmaxf(sm[0], sm[1]), fmaxf(sm[2], sm[3]));
    float S = 0.f, A = 0.f;
#pragma unroll
    for (int w = 0; w < 4; w++) {
        float sc = __expf(sm[w] - M);
        S += ss[w] * sc;
        A += sacc[w][t] * sc;
    }
    float o_t = A / (S + 1e-16f) + bias[t];   // hidden value, channel t

    // fused output head: out[node,o] = sum_t o_t * oW[t,o] + ob[o]
    float p[10];
#pragma unroll
    for (int o = 0; o < 10; o++) p[o] = o_t * oW[t * 10 + o];
#pragma unroll
    for (int off = 16; off; off >>= 1)
#pragma unroll
        for (int o = 0; o < 10; o++) p[o] += __shfl_xor_sync(0xffffffffu, p[o], off);
    __shared__ float pp[4][10];
    if (!lane)
#pragma unroll
        for (int o = 0; o < 10; o++) pp[warp][o] = p[o];
    __syncthreads();
    if (t < 10) {
        float v = ob[t];
#pragma unroll
        for (int w = 0; w < 4; w++) v += pp[w][t];
        out[(size_t)node * 10 + t] = v;
    }
}

// ---------------- launch ----------------------------------------------------
extern "C" void kernel_launch(void* const* d_in, const int* in_sizes, int n_in,
                              void* d_out, int out_size) {
    const float* xp   = (const float*)d_in[0];
    const int*   ei   = (const int*)  d_in[1];
    const float* emb  = (const float*)d_in[2];
    const float* pW   = (const float*)d_in[3];
    const float* pb   = (const float*)d_in[4];
    const float* W1l  = (const float*)d_in[5];
    const float* W1r  = (const float*)d_in[6];
    const float* att1 = (const float*)d_in[7];
    const float* b1   = (const float*)d_in[8];
    const float* W2l  = (const float*)d_in[9];
    const float* W2r  = (const float*)d_in[10];
    const float* att2 = (const float*)d_in[11];
    const float* b2   = (const float*)d_in[12];
    const float* oW   = (const float*)d_in[13];
    const float* ob   = (const float*)d_in[14];
    float* out = (float*)d_out;

    int n  = in_sizes[0] / 65;
    int ne = in_sizes[1] / 2;
    int et = ne + n;

    float *x0, *xl1, *xr1, *agg1, *xl2, *xr2;
    int *deg, *cursor, *rowptr, *esrc;
    cudaGetSymbolAddress((void**)&x0,   g_x0);
    cudaGetSymbolAddress((void**)&xl1,  g_xl1);
    cudaGetSymbolAddress((void**)&xr1,  g_xr1);
    cudaGetSymbolAddress((void**)&agg1, g_agg1);
    cudaGetSymbolAddress((void**)&xl2,  g_xl2);
    cudaGetSymbolAddress((void**)&xr2,  g_xr2);
    cudaGetSymbolAddress((void**)&deg,    g_deg);
    cudaGetSymbolAddress((void**)&cursor, g_cursor);
    cudaGetSymbolAddress((void**)&rowptr, g_rowptr);
    cudaGetSymbolAddress((void**)&esrc,   g_esrc);

    cudaFuncSetAttribute(k_gemm<true>,  cudaFuncAttributeMaxDynamicSharedMemorySize, GEMM_SMEM);
    cudaFuncSetAttribute(k_gemm<false>, cudaFuncAttributeMaxDynamicSharedMemorySize, GEMM_SMEM);

    const int TB = 256;
    int gm = (n + 63) / 64;

    // ---- CSR build ----
    cudaMemsetAsync(deg, 0, (size_t)(n + 1) * sizeof(int));
    cudaMemsetAsync(cursor, 0, (size_t)n * sizeof(int));
    k_hist<<<(et + TB - 1) / TB, TB>>>(ei, deg, ne, n);
    k_scan<<<1, 1024>>>(deg, rowptr, n);
    k_scatter<<<(et + TB - 1) / TB, TB>>>(ei, rowptr, cursor, esrc, ne, n);

    // ---- proj (fused embed-gather) -> x0 : N=128 -> 2 n-tiles ----
    k_gemm<true><<<dim3(2, gm), TB, GEMM_SMEM>>>(nullptr, pW, nullptr, pb, x0, nullptr,
                                                 n, 128, 192, 1, 2, xp, emb);

    // ---- layer 1: xl1 | xr1 in one launch : N=512 -> 8 tiles each ----
    k_gemm<false><<<dim3(16, gm), TB, GEMM_SMEM>>>(x0, W1l, W1r, nullptr, xl1, xr1,
                                                   n, 512, 128, 0, 8, nullptr, nullptr);
    k_fused1<<<n, 128>>>(xl1, xr1, rowptr, esrc, att1, b1, agg1);

    // ---- layer 2: xl2 | xr2 in one launch : N=128 -> 2 tiles each ----
    k_gemm<false><<<dim3(4, gm), TB, GEMM_SMEM>>>(agg1, W2l, W2r, nullptr, xl2, xr2,
                                                  n, 128, 512, 0, 2, nullptr, nullptr);
    k_fused2<<<n, 128>>>(xl2, xr2, rowptr, esrc, att2, b2, oW, ob, out);
}

// round 15
// speedup vs baseline: 1.3053x; 1.3053x over previous
#include <cuda_runtime.h>
#include <cuda_bf16.h>
#include <math.h>

// Problem constants (fixed shapes per reference)
#define NN   20000
#define EE   320000
#define ETOT (EE + NN)     // edges + self loops

// ---------------- scratch (device globals; no allocation allowed) ----------
__device__ float g_x0  [NN * 128];
__device__ float g_xl1 [NN * 512];
__device__ float g_xr1 [NN * 512];
__device__ float g_agg1[NN * 512];
__device__ float g_xl2 [NN * 128];
__device__ float g_xr2 [NN * 128];
// CSR scratch
__device__ int   g_deg   [NN + 1];
__device__ int   g_cursor[NN];
__device__ int   g_rowptr[NN + 1];
__device__ int   g_esrc  [ETOT];

// ---------------- bf16 helpers ----------------------------------------------
__device__ __forceinline__ void split_pack(float x, float y, unsigned& hw, unsigned& lw) {
    __nv_bfloat16 h0 = __float2bfloat16_rn(x);
    __nv_bfloat16 h1 = __float2bfloat16_rn(y);
    __nv_bfloat16 l0 = __float2bfloat16_rn(x - __bfloat162float(h0));
    __nv_bfloat16 l1 = __float2bfloat16_rn(y - __bfloat162float(h1));
    hw = (unsigned)__bfloat16_as_ushort(h0) | ((unsigned)__bfloat16_as_ushort(h1) << 16);
    lw = (unsigned)__bfloat16_as_ushort(l0) | ((unsigned)__bfloat16_as_ushort(l1) << 16);
}

__device__ __forceinline__ void mma_bf16(float* d, const unsigned* a, const unsigned* b) {
    asm volatile(
        "mma.sync.aligned.m16n8k16.row.col.f32.bf16.bf16.f32 "
        "{%0,%1,%2,%3}, {%4,%5,%6,%7}, {%8,%9}, {%0,%1,%2,%3};"
        : "+f"(d[0]), "+f"(d[1]), "+f"(d[2]), "+f"(d[3])
        : "r"(a[0]), "r"(a[1]), "r"(a[2]), "r"(a[3]), "r"(b[0]), "r"(b[1]));
}

// ---------------- GEMM: 64x128 tile, 2-way-split BF16, double-buffered -------
// C[M,N] = act(A @ B + bias). Grid.x covers nx n-tiles for (B1,C1) and, if
// B2 != null, nx more for (B2,C2) — merges the l/r weight GEMMs (shared A).
// GATHER builds A rows on the fly: cols 0..127 = emb[id[r]], cols 128.. = feats.
// Requires N % 128 == 0, K % 16 == 0. Dynamic smem = 26624 bytes.
// Smem planes are word-indexed [kp][row/col], kp = k/2, each word = (bf16 k, bf16 k+1).
#define GEMM_SMEM 26624
template <bool GATHER>
__global__ void __launch_bounds__(256, 2)
k_gemm(const float* __restrict__ A,
       const float* __restrict__ B1, const float* __restrict__ B2,
       const float* __restrict__ bias,
       float* __restrict__ C1, float* __restrict__ C2,
       int M, int N, int K, int relu, int nx,
       const float* __restrict__ xp, const float* __restrict__ emb) {
    extern __shared__ unsigned smu[];
    const int ASTR = 72, BSTR = 136;
    const int ASZ = 8 * ASTR;               // 576 words  (A: 8 kp x 64 rows)
    const int BSZ = 8 * BSTR;               // 1088 words (B: 8 kp x 128 cols)
    const int BUFSZ = 2 * ASZ + 2 * BSZ;    // 3328 words per buffer

    int tid  = threadIdx.x;                 // 256 threads = 8 warps
    int lane = tid & 31;
    int warp = tid >> 5;
    int wm = warp >> 2;                     // 0..1 : 32-row slab
    int wn = warp & 3;                      // 0..3 : 32-col slab
    int g  = lane >> 2;                     // group 0..7
    int tg = lane & 3;                      // thread-in-group 0..3

    int bxr = blockIdx.x;
    bool sel = bxr >= nx;
    const float* B = sel ? B2 : B1;
    float* C = sel ? C2 : C1;
    int bn = (sel ? bxr - nx : bxr) * 128;
    int bm = blockIdx.y * 64;

    float acc[2][4][4] = {};                // [mt][nt][c0..c3]

    // A staging roles: row + 4 consecutive k
    int ar = tid >> 2;                      // 0..63
    int ac = (tid & 3) * 4;                 // 0,4,8,12
    // B staging roles: k-pair + 4 consecutive cols
    int bkp  = tid >> 5;                    // 0..7
    int bcol = (tid & 31) * 4;              // 0..124
    bool aok = (bm + ar) < M;
    const float* Ap = GATHER ? nullptr : A + (size_t)(bm + ar) * K + ac;
    int gid = 0;
    if (GATHER && aok) gid = (int)xp[(size_t)(bm + ar) * 65];

    float av[4], bv0[4], bv1[4];
    auto loadTile = [&](int k0) {
        if (aok) {
            if (GATHER) {
                int kc = k0 + ac;
                if (kc < 128) {
                    float4 v = *(const float4*)(emb + (size_t)gid * 128 + kc);
                    av[0] = v.x; av[1] = v.y; av[2] = v.z; av[3] = v.w;
                } else {
                    const float* p = xp + (size_t)(bm + ar) * 65 + 1 + (kc - 128);
                    av[0] = p[0]; av[1] = p[1]; av[2] = p[2]; av[3] = p[3];
                }
            } else {
                float4 v = *(const float4*)(Ap + k0);
                av[0] = v.x; av[1] = v.y; av[2] = v.z; av[3] = v.w;
            }
        } else {
            av[0] = av[1] = av[2] = av[3] = 0.f;
        }
        float4 v0 = *(const float4*)(B + (size_t)(k0 + 2 * bkp)     * N + bn + bcol);
        float4 v1 = *(const float4*)(B + (size_t)(k0 + 2 * bkp + 1) * N + bn + bcol);
        bv0[0] = v0.x; bv0[1] = v0.y; bv0[2] = v0.z; bv0[3] = v0.w;
        bv1[0] = v1.x; bv1[1] = v1.y; bv1[2] = v1.z; bv1[3] = v1.w;
    };

    auto stage = [&](int buf) {
        unsigned* Ah = smu + buf * BUFSZ;
        unsigned* Al = Ah + ASZ;
        unsigned* Bh = Al + ASZ;
        unsigned* Bl = Bh + BSZ;
#pragma unroll
        for (int i = 0; i < 4; i += 2) {
            unsigned hw, lw;
            split_pack(av[i], av[i + 1], hw, lw);
            int kp = (ac + i) >> 1;
            Ah[kp * ASTR + ar] = hw;
            Al[kp * ASTR + ar] = lw;
        }
#pragma unroll
        for (int j = 0; j < 4; j++) {
            unsigned hw, lw;
            split_pack(bv0[j], bv1[j], hw, lw);   // pair along k: (k, k+1) of col bcol+j
            Bh[bkp * BSTR + bcol + j] = hw;
            Bl[bkp * BSTR + bcol + j] = lw;
        }
    };

    auto compute = [&](int buf) {
        const unsigned* Ah = smu + buf * BUFSZ;
        const unsigned* Al = Ah + ASZ;
        const unsigned* Bh = Al + ASZ;
        const unsigned* Bl = Bh + BSZ;
        // B fragments for the 4 n-tiles
        unsigned bhf[4][2], blf[4][2];
#pragma unroll
        for (int nt = 0; nt < 4; nt++) {
            int col = wn * 32 + nt * 8 + g;
            bhf[nt][0] = Bh[tg * BSTR + col];
            bhf[nt][1] = Bh[(tg + 4) * BSTR + col];
            blf[nt][0] = Bl[tg * BSTR + col];
            blf[nt][1] = Bl[(tg + 4) * BSTR + col];
        }
#pragma unroll
        for (int mt = 0; mt < 2; mt++) {
            int row = wm * 32 + mt * 16 + g;
            unsigned ahf[4], alf[4];
            ahf[0] = Ah[tg * ASTR + row];
            ahf[1] = Ah[tg * ASTR + row + 8];
            ahf[2] = Ah[(tg + 4) * ASTR + row];
            ahf[3] = Ah[(tg + 4) * ASTR + row + 8];
            alf[0] = Al[tg * ASTR + row];
            alf[1] = Al[tg * ASTR + row + 8];
            alf[2] = Al[(tg + 4) * ASTR + row];
            alf[3] = Al[(tg + 4) * ASTR + row + 8];
#pragma unroll
            for (int nt = 0; nt < 4; nt++) {
                mma_bf16(acc[mt][nt], ahf, bhf[nt]);   // hi*hi
                mma_bf16(acc[mt][nt], ahf, blf[nt]);   // hi*lo
                mma_bf16(acc[mt][nt], alf, bhf[nt]);   // lo*hi
            }
        }
    };

    int kiters = K >> 4;
    loadTile(0);
    stage(0);
    __syncthreads();
    for (int it = 0; it < kiters; ++it) {
        int buf = it & 1;
        bool have = (it + 1 < kiters);
        if (have) loadTile((it + 1) << 4);
        compute(buf);
        if (have) stage(buf ^ 1);
        __syncthreads();
    }

    // ---- epilogue ----
#pragma unroll
    for (int mt = 0; mt < 2; mt++) {
        int r0 = bm + wm * 32 + mt * 16 + g;
#pragma unroll
        for (int nt = 0; nt < 4; nt++) {
            int c0 = bn + wn * 32 + nt * 8 + tg * 2;
            float v0 = acc[mt][nt][0], v1 = acc[mt][nt][1];
            float v2 = acc[mt][nt][2], v3 = acc[mt][nt][3];
            if (bias) {
                v0 += bias[c0]; v1 += bias[c0 + 1];
                v2 += bias[c0]; v3 += bias[c0 + 1];
            }
            if (relu) {
                v0 = fmaxf(v0, 0.f); v1 = fmaxf(v1, 0.f);
                v2 = fmaxf(v2, 0.f); v3 = fmaxf(v3, 0.f);
            }
            if (r0 < M)     *(float2*)(C + (size_t)r0 * N + c0)       = make_float2(v0, v1);
            if (r0 + 8 < M) *(float2*)(C + (size_t)(r0 + 8) * N + c0) = make_float2(v2, v3);
        }
    }
}

// ---------------- CSR build --------------------------------------------------
__global__ void k_hist(const int* __restrict__ ei, int* __restrict__ deg, int ne, int nn) {
    int i = blockIdx.x * blockDim.x + threadIdx.x;
    int tot = ne + nn;
    if (i >= tot) return;
    int d = (i < ne) ? ei[ne + i] : i - ne;
    atomicAdd(&deg[d], 1);
}

// single-block warp-shuffle scan (1024 threads = 32 warps)
__global__ void k_scan(const int* __restrict__ deg, int* __restrict__ rowptr, int n) {
    __shared__ int wsum[32];
    __shared__ int carry_s;
    int t = threadIdx.x, lane = t & 31, wid = t >> 5;
    if (t == 0) carry_s = 0;
    __syncthreads();
    for (int base = 0; base < n; base += 1024) {
        int i = base + t;
        int carry = carry_s;
        int v = (i < n) ? deg[i] : 0;
        int x = v;
#pragma unroll
        for (int o = 1; o < 32; o <<= 1) {
            int y = __shfl_up_sync(0xffffffffu, x, o);
            if (lane >= o) x += y;
        }
        if (lane == 31) wsum[wid] = x;
        __syncthreads();
        if (wid == 0) {
            int s = wsum[lane];
#pragma unroll
            for (int o = 1; o < 32; o <<= 1) {
                int y = __shfl_up_sync(0xffffffffu, s, o);
                if (lane >= o) s += y;
            }
            wsum[lane] = s;
        }
        __syncthreads();
        int woff = wid ? wsum[wid - 1] : 0;
        if (i < n) rowptr[i] = carry + woff + x - v;   // exclusive
        int total = wsum[31];
        __syncthreads();
        if (t == 0) carry_s = carry + total;
        __syncthreads();
    }
    if (t == 0) rowptr[n] = carry_s;
}

__global__ void k_scatter(const int* __restrict__ ei, const int* __restrict__ rowptr,
                          int* __restrict__ cursor, int* __restrict__ esrc,
                          int ne, int nn) {
    int i = blockIdx.x * blockDim.x + threadIdx.x;
    int tot = ne + nn;
    if (i >= tot) return;
    int s, d;
    if (i < ne) { s = ei[i]; d = ei[ne + i]; } else { s = d = i - ne; }
    int pos = rowptr[d] + atomicAdd(&cursor[d], 1);
    esrc[pos] = s;
}

// ---------------- fused GATv2 edge phase (flash-style online softmax) --------
// Layer 1: 4 heads x 128 ch. Block = 128 threads (4 warps) per node.
__global__ void k_fused1(const float* __restrict__ xl, const float* __restrict__ xr,
                         const int* __restrict__ rowptr, const int* __restrict__ esrc,
                         const float* __restrict__ att, const float* __restrict__ bias,
                         float* __restrict__ out) {
    int node = blockIdx.x;
    int t = threadIdx.x, warp = t >> 5, lane = t & 31;
    int beg = rowptr[node], end = rowptr[node + 1];

    float xrv[16], attv[16];
    const float* pxr = xr + (size_t)node * 512;
#pragma unroll
    for (int i = 0; i < 16; i++) {
        int c = i * 32 + lane;
        xrv[i] = pxr[c];
        attv[i] = att[c];
    }
    float m[4] = {-INFINITY, -INFINITY, -INFINITY, -INFINITY};
    float s[4] = {0.f, 0.f, 0.f, 0.f};
    float acc[16] = {};

    for (int j = beg + warp; j < end; j += 4) {
        const float* px = xl + (size_t)esrc[j] * 512;
        float xv[16], p[4] = {0.f, 0.f, 0.f, 0.f};
#pragma unroll
        for (int i = 0; i < 16; i++) {
            xv[i] = px[i * 32 + lane];
            float v = xv[i] + xrv[i];
            v = v > 0.f ? v : 0.2f * v;
            p[i >> 2] += v * attv[i];
        }
#pragma unroll
        for (int o = 16; o; o >>= 1) {
            p[0] += __shfl_xor_sync(0xffffffffu, p[0], o);
            p[1] += __shfl_xor_sync(0xffffffffu, p[1], o);
            p[2] += __shfl_xor_sync(0xffffffffu, p[2], o);
            p[3] += __shfl_xor_sync(0xffffffffu, p[3], o);
        }
#pragma unroll
        for (int h = 0; h < 4; h++) {
            float e = p[h];
            float mn = fmaxf(m[h], e);
            float sc = __expf(m[h] - mn);       // first edge: exp(-inf)=0
            float w  = __expf(e - mn);
            s[h] = s[h] * sc + w;
            m[h] = mn;
#pragma unroll
            for (int i = 0; i < 4; i++) {
                int ii = h * 4 + i;
                acc[ii] = acc[ii] * sc + w * xv[ii];
            }
        }
    }

    __shared__ float sm[4][4], ss[4][4];
    __shared__ float sacc[4][512];
    if (lane < 4) { sm[warp][lane] = m[lane]; ss[warp][lane] = s[lane]; }
#pragma unroll
    for (int i = 0; i < 16; i++) sacc[warp][i * 32 + lane] = acc[i];
    __syncthreads();

#pragma unroll
    for (int h = 0; h < 4; h++) {
        int c = h * 128 + t;
        float M = fmaxf(fmaxf(sm[0][h], sm[1][h]), fmaxf(sm[2][h], sm[3][h]));
        float S = 0.f, A = 0.f;
#pragma unroll
        for (int w = 0; w < 4; w++) {
            float sc = __expf(sm[w][h] - M);    // empty warp: m=-inf -> 0
            S += ss[w][h] * sc;
            A += sacc[w][c] * sc;
        }
        out[(size_t)node * 512 + c] = fmaxf(A / (S + 1e-16f) + bias[c], 0.f);
    }
}

// Layer 2 (1 head x 128 ch) + fused output head: out[node,10].
__global__ void k_fused2(const float* __restrict__ xl, const float* __restrict__ xr,
                         const int* __restrict__ rowptr, const int* __restrict__ esrc,
                         const float* __restrict__ att, const float* __restrict__ bias,
                         const float* __restrict__ oW, const float* __restrict__ ob,
                         float* __restrict__ out) {
    int node = blockIdx.x;
    int t = threadIdx.x, warp = t >> 5, lane = t & 31;
    int beg = rowptr[node], end = rowptr[node + 1];

    float xrv[4], attv[4];
    const float* pxr = xr + (size_t)node * 128;
#pragma unroll
    for (int i = 0; i < 4; i++) {
        int c = i * 32 + lane;
        xrv[i] = pxr[c];
        attv[i] = att[c];
    }
    float m = -INFINITY, s = 0.f;
    float acc[4] = {};

    for (int j = beg + warp; j < end; j += 4) {
        const float* px = xl + (size_t)esrc[j] * 128;
        float xv[4], p = 0.f;
#pragma unroll
        for (int i = 0; i < 4; i++) {
            xv[i] = px[i * 32 + lane];
            float v = xv[i] + xrv[i];
            v = v > 0.f ? v : 0.2f * v;
            p += v * attv[i];
        }
#pragma unroll
        for (int o = 16; o; o >>= 1) p += __shfl_xor_sync(0xffffffffu, p, o);
        float mn = fmaxf(m, p);
        float sc = __expf(m - mn);
        float w  = __expf(p - mn);
        s = s * sc + w;
        m = mn;
#pragma unroll
        for (int i = 0; i < 4; i++) acc[i] = acc[i] * sc + w * xv[i];
    }

    __shared__ float sm[4], ss[4];
    __shared__ float sacc[4][128];
    if (!lane) { sm[warp] = m; ss[warp] = s; }
#pragma unroll
    for (int i = 0; i < 4; i++) sacc[warp][i * 32 + lane] = acc[i];
    __syncthreads();

    float M = fmaxf(fmaxf(sm[0], sm[1]), fmaxf(sm[2], sm[3]));
    float S = 0.f, A = 0.f;
#pragma unroll
    for (int w = 0; w < 4; w++) {
        float sc = __expf(sm[w] - M);
        S += ss[w] * sc;
        A += sacc[w][t] * sc;
    }
    float o_t = A / (S + 1e-16f) + bias[t];   // hidden value, channel t

    // fused output head: out[node,o] = sum_t o_t * oW[t,o] + ob[o]
    float p[10];
#pragma unroll
    for (int o = 0; o < 10; o++) p[o] = o_t * oW[t * 10 + o];
#pragma unroll
    for (int off = 16; off; off >>= 1)
#pragma unroll
        for (int o = 0; o < 10; o++) p[o] += __shfl_xor_sync(0xffffffffu, p[o], off);
    __shared__ float pp[4][10];
    if (!lane)
#pragma unroll
        for (int o = 0; o < 10; o++) pp[warp][o] = p[o];
    __syncthreads();
    if (t < 10) {
        float v = ob[t];
#pragma unroll
        for (int w = 0; w < 4; w++) v += pp[w][t];
        out[(size_t)node * 10 + t] = v;
    }
}

// ---------------- launch ----------------------------------------------------
extern "C" void kernel_launch(void* const* d_in, const int* in_sizes, int n_in,
                              void* d_out, int out_size) {
    const float* xp   = (const float*)d_in[0];
    const int*   ei   = (const int*)  d_in[1];
    const float* emb  = (const float*)d_in[2];
    const float* pW   = (const float*)d_in[3];
    const float* pb   = (const float*)d_in[4];
    const float* W1l  = (const float*)d_in[5];
    const float* W1r  = (const float*)d_in[6];
    const float* att1 = (const float*)d_in[7];
    const float* b1   = (const float*)d_in[8];
    const float* W2l  = (const float*)d_in[9];
    const float* W2r  = (const float*)d_in[10];
    const float* att2 = (const float*)d_in[11];
    const float* b2   = (const float*)d_in[12];
    const float* oW   = (const float*)d_in[13];
    const float* ob   = (const float*)d_in[14];
    float* out = (float*)d_out;

    int n  = in_sizes[0] / 65;
    int ne = in_sizes[1] / 2;
    int et = ne + n;

    float *x0, *xl1, *xr1, *agg1, *xl2, *xr2;
    int *deg, *cursor, *rowptr, *esrc;
    cudaGetSymbolAddress((void**)&x0,   g_x0);
    cudaGetSymbolAddress((void**)&xl1,  g_xl1);
    cudaGetSymbolAddress((void**)&xr1,  g_xr1);
    cudaGetSymbolAddress((void**)&agg1, g_agg1);
    cudaGetSymbolAddress((void**)&xl2,  g_xl2);
    cudaGetSymbolAddress((void**)&xr2,  g_xr2);
    cudaGetSymbolAddress((void**)&deg,    g_deg);
    cudaGetSymbolAddress((void**)&cursor, g_cursor);
    cudaGetSymbolAddress((void**)&rowptr, g_rowptr);
    cudaGetSymbolAddress((void**)&esrc,   g_esrc);

    const int TB = 256;
    int gm = (n + 63) / 64;

    // ---- CSR build ----
    cudaMemsetAsync(deg, 0, (size_t)(n + 1) * sizeof(int));
    cudaMemsetAsync(cursor, 0, (size_t)n * sizeof(int));
    k_hist<<<(et + TB - 1) / TB, TB>>>(ei, deg, ne, n);
    k_scan<<<1, 1024>>>(deg, rowptr, n);
    k_scatter<<<(et + TB - 1) / TB, TB>>>(ei, rowptr, cursor, esrc, ne, n);

    // ---- proj (fused embed-gather) -> x0 ----
    k_gemm<true><<<dim3(1, gm), TB, GEMM_SMEM>>>(nullptr, pW, nullptr, pb, x0, nullptr,
                                                 n, 128, 192, 1, 1, xp, emb);

    // ---- layer 1: xl1 | xr1 in one launch ----
    k_gemm<false><<<dim3(8, gm), TB, GEMM_SMEM>>>(x0, W1l, W1r, nullptr, xl1, xr1,
                                                  n, 512, 128, 0, 4, nullptr, nullptr);
    k_fused1<<<n, 128>>>(xl1, xr1, rowptr, esrc, att1, b1, agg1);

    // ---- layer 2: xl2 | xr2 in one launch ----
    k_gemm<false><<<dim3(2, gm), TB, GEMM_SMEM>>>(agg1, W2l, W2r, nullptr, xl2, xr2,
                                                  n, 128, 512, 0, 1, nullptr, nullptr);
    k_fused2<<<n, 128>>>(xl2, xr2, rowptr, esrc, att2, b2, oW, ob, out);
}

// round 17
// speedup vs baseline: 1.3460x; 1.0312x over previous
#include <cuda_runtime.h>
#include <cuda_bf16.h>
#include <math.h>

// Problem constants (fixed shapes per reference)
#define NN   20000
#define EE   320000
#define ETOT (EE + NN)     // edges + self loops

// ---------------- scratch (device globals; no allocation allowed) ----------
// packed bf16 hi/lo planes (word = (bf16 k, bf16 k+1)); lo plane at +PL words
__device__ unsigned g_combq[NN * 96 * 2];
__device__ unsigned g_x0q  [NN * 64 * 2];
__device__ unsigned g_agg1q[NN * 256 * 2];
__device__ unsigned g_pWq  [96 * 128 * 2];
__device__ unsigned g_W1lq [64 * 512 * 2];
__device__ unsigned g_W1rq [64 * 512 * 2];
__device__ unsigned g_W2lq [256 * 128 * 2];
__device__ unsigned g_W2rq [256 * 128 * 2];
__device__ float g_xl1 [NN * 512];
__device__ float g_xr1 [NN * 512];
__device__ float g_xl2 [NN * 128];
__device__ float g_xr2 [NN * 128];
// CSR scratch
__device__ int   g_deg   [NN + 1];
__device__ int   g_cursor[NN];
__device__ int   g_rowptr[NN + 1];
__device__ int   g_esrc  [ETOT];

// ---------------- bf16 helpers ----------------------------------------------
__device__ __forceinline__ void split_pack(float x, float y, unsigned& hw, unsigned& lw) {
    __nv_bfloat16 h0 = __float2bfloat16_rn(x);
    __nv_bfloat16 h1 = __float2bfloat16_rn(y);
    __nv_bfloat16 l0 = __float2bfloat16_rn(x - __bfloat162float(h0));
    __nv_bfloat16 l1 = __float2bfloat16_rn(y - __bfloat162float(h1));
    hw = (unsigned)__bfloat16_as_ushort(h0) | ((unsigned)__bfloat16_as_ushort(h1) << 16);
    lw = (unsigned)__bfloat16_as_ushort(l0) | ((unsigned)__bfloat16_as_ushort(l1) << 16);
}

__device__ __forceinline__ void mma_bf16(float* d, const unsigned* a, const unsigned* b) {
    asm volatile(
        "mma.sync.aligned.m16n8k16.row.col.f32.bf16.bf16.f32 "
        "{%0,%1,%2,%3}, {%4,%5,%6,%7}, {%8,%9}, {%0,%1,%2,%3};"
        : "+f"(d[0]), "+f"(d[1]), "+f"(d[2]), "+f"(d[3])
        : "r"(a[0]), "r"(a[1]), "r"(a[2]), "r"(a[3]), "r"(b[0]), "r"(b[1]));
}

// ---------------- pre-split kernels ------------------------------------------
// weights: W fp32 [2*Kw x N] row-major -> Wq words [kp*N + n], lo at +Kw*N
__global__ void k_wsplit(const float* __restrict__ W, unsigned* __restrict__ Wq,
                         int Kw, int N) {
    int i = blockIdx.x * blockDim.x + threadIdx.x;
    if (i >= Kw * N) return;
    int kp = i / N, n = i - kp * N;
    unsigned hw, lw;
    split_pack(W[(size_t)(2 * kp) * N + n], W[(size_t)(2 * kp + 1) * N + n], hw, lw);
    Wq[i] = hw;
    Wq[(size_t)Kw * N + i] = lw;
}

// combined features: row r, cols 0..127 = emb[id[r]], 128..191 = feats
__global__ void k_combsplit(const float* __restrict__ xp, const float* __restrict__ emb,
                            unsigned* __restrict__ q, int n) {
    int i = blockIdx.x * blockDim.x + threadIdx.x;
    if (i >= n * 96) return;
    int row = i / 96, kp = i - row * 96;
    int c0 = 2 * kp;
    float x0v, x1v;
    if (c0 < 128) {
        int id = (int)xp[(size_t)row * 65];
        x0v = emb[(size_t)id * 128 + c0];
        x1v = emb[(size_t)id * 128 + c0 + 1];
    } else {
        const float* p = xp + (size_t)row * 65 + 1 + (c0 - 128);
        x0v = p[0]; x1v = p[1];
    }
    unsigned hw, lw;
    split_pack(x0v, x1v, hw, lw);
    q[i] = hw;
    q[(size_t)NN * 96 + i] = lw;
}

// ---------------- GEMM: 64x128 tile, pre-split BF16 + cp.async ---------------
// C[M,N] = act(A @ B + bias). Grid.x covers nx n-tiles for (B1,C1) and, if
// B2 != null, nx more for (B2,C2). A/B are pre-split word arrays (hi, lo at +PL).
// SPLITOUT writes C as packed hi/lo words (for the next GEMM's A) instead of fp32.
// Requires N % 128 == 0, K % 16 == 0. Dynamic smem = 29696 bytes.
#define GEMM_SMEM 29696
template <bool SPLITOUT>
__global__ void __launch_bounds__(256, 3)
k_gemm(const unsigned* __restrict__ Aq, int aPL, int aStride,
       const unsigned* __restrict__ B1q, const unsigned* __restrict__ B2q, int bPL,
       const float* __restrict__ bias,
       float* __restrict__ C1, float* __restrict__ C2,
       unsigned* __restrict__ Cq, int cPL,
       int M, int N, int K, int relu, int nx) {
    extern __shared__ unsigned smu[];
    // buffer layout (words): Ah[64][12] | Al[64][12] | Bh[8][136] | Bl[8][136]
    const int BUFSZ = 3712;
    const int A_LO = 768, B_HI = 1536, B_LO = 2624;

    int tid = threadIdx.x, lane = tid & 31, warp = tid >> 5;
    int wm = warp >> 2, wn = warp & 3;      // 32-row / 32-col slabs
    int g = lane >> 2, tg = lane & 3;

    int bxr = blockIdx.x;
    bool sel = bxr >= nx;
    const unsigned* Bq = sel ? B2q : B1q;
    float* C = sel ? C2 : C1;
    int bn = (sel ? bxr - nx : bxr) * 128;
    int bm = blockIdx.y * 64;

    // async staging roles
    int aplane = tid >> 7;                  // 0=hi 1=lo
    int arow = (tid & 127) >> 1;            // 0..63
    int ahalf = tid & 1;                    // 0/1 -> kp 0..3 / 4..7
    int bkp = tid >> 5;                     // 0..7
    int bcols = (tid & 31) * 4;             // 0..124
    bool aok = (bm + arow) < M;
    int arowc = aok ? (bm + arow) : 0;
    unsigned sb = (unsigned)__cvta_generic_to_shared(smu);

    float acc[2][4][4] = {};

    auto loadAsync = [&](int it, int buf) {
        unsigned base = sb + buf * BUFSZ * 4;
        const unsigned* asrc = Aq + (size_t)aplane * aPL + (size_t)arowc * aStride
                                  + it * 8 + ahalf * 4;
        unsigned adst = base + (aplane * A_LO + arow * 12 + ahalf * 4) * 4;
        asm volatile("cp.async.cg.shared.global [%0], [%1], 16, %2;"
                     :: "r"(adst), "l"(asrc), "r"(aok ? 16 : 0));
#pragma unroll
        for (int p = 0; p < 2; p++) {
            const unsigned* bsrc = Bq + (size_t)p * bPL + (size_t)(it * 8 + bkp) * N
                                      + bn + bcols;
            unsigned bdst = base + (B_HI + p * 1088 + bkp * 136 + bcols) * 4;
            asm volatile("cp.async.cg.shared.global [%0], [%1], 16;"
                         :: "r"(bdst), "l"(bsrc));
        }
        asm volatile("cp.async.commit_group;");
    };

    auto compute = [&](int buf) {
        const unsigned* Ah = smu + buf * BUFSZ;
        const unsigned* Al = Ah + A_LO;
        const unsigned* Bh = smu + buf * BUFSZ + B_HI;
        const unsigned* Bl = smu + buf * BUFSZ + B_LO;
        unsigned bhf[4][2], blf[4][2];
#pragma unroll
        for (int nt = 0; nt < 4; nt++) {
            int col = wn * 32 + nt * 8 + g;
            bhf[nt][0] = Bh[tg * 136 + col];
            bhf[nt][1] = Bh[(tg + 4) * 136 + col];
            blf[nt][0] = Bl[tg * 136 + col];
            blf[nt][1] = Bl[(tg + 4) * 136 + col];
        }
#pragma unroll
        for (int mt = 0; mt < 2; mt++) {
            int row = wm * 32 + mt * 16 + g;
            unsigned ahf[4], alf[4];
            ahf[0] = Ah[row * 12 + tg];
            ahf[1] = Ah[(row + 8) * 12 + tg];
            ahf[2] = Ah[row * 12 + tg + 4];
            ahf[3] = Ah[(row + 8) * 12 + tg + 4];
            alf[0] = Al[row * 12 + tg];
            alf[1] = Al[(row + 8) * 12 + tg];
            alf[2] = Al[row * 12 + tg + 4];
            alf[3] = Al[(row + 8) * 12 + tg + 4];
#pragma unroll
            for (int nt = 0; nt < 4; nt++) {
                mma_bf16(acc[mt][nt], ahf, bhf[nt]);   // hi*hi
                mma_bf16(acc[mt][nt], ahf, blf[nt]);   // hi*lo
                mma_bf16(acc[mt][nt], alf, bhf[nt]);   // lo*hi
            }
        }
    };

    int kiters = K >> 4;
    loadAsync(0, 0);
    for (int it = 0; it < kiters; ++it) {
        asm volatile("cp.async.wait_group 0;");
        __syncthreads();
        if (it + 1 < kiters) loadAsync(it + 1, (it + 1) & 1);
        compute(it & 1);
    }

    // ---- epilogue ----
#pragma unroll
    for (int mt = 0; mt < 2; mt++) {
        int r0 = bm + wm * 32 + mt * 16 + g;
#pragma unroll
        for (int nt = 0; nt < 4; nt++) {
            int c0 = bn + wn * 32 + nt * 8 + tg * 2;
            float v0 = acc[mt][nt][0], v1 = acc[mt][nt][1];
            float v2 = acc[mt][nt][2], v3 = acc[mt][nt][3];
            if (bias) {
                v0 += bias[c0]; v1 += bias[c0 + 1];
                v2 += bias[c0]; v3 += bias[c0 + 1];
            }
            if (relu) {
                v0 = fmaxf(v0, 0.f); v1 = fmaxf(v1, 0.f);
                v2 = fmaxf(v2, 0.f); v3 = fmaxf(v3, 0.f);
            }
            if (SPLITOUT) {
                int Nw = N >> 1, w = c0 >> 1;
                if (r0 < M) {
                    unsigned hw, lw;
                    split_pack(v0, v1, hw, lw);
                    Cq[(size_t)r0 * Nw + w] = hw;
                    Cq[(size_t)cPL + (size_t)r0 * Nw + w] = lw;
                }
                if (r0 + 8 < M) {
                    unsigned hw, lw;
                    split_pack(v2, v3, hw, lw);
                    Cq[(size_t)(r0 + 8) * Nw + w] = hw;
                    Cq[(size_t)cPL + (size_t)(r0 + 8) * Nw + w] = lw;
                }
            } else {
                if (r0 < M)     *(float2*)(C + (size_t)r0 * N + c0)       = make_float2(v0, v1);
                if (r0 + 8 < M) *(float2*)(C + (size_t)(r0 + 8) * N + c0) = make_float2(v2, v3);
            }
        }
    }
}

// ---------------- CSR build --------------------------------------------------
__global__ void k_hist(const int* __restrict__ ei, int* __restrict__ deg, int ne, int nn) {
    int i = blockIdx.x * blockDim.x + threadIdx.x;
    int tot = ne + nn;
    if (i >= tot) return;
    int d = (i < ne) ? ei[ne + i] : i - ne;
    atomicAdd(&deg[d], 1);
}

__global__ void k_scan(const int* __restrict__ deg, int* __restrict__ rowptr, int n) {
    __shared__ int wsum[32];
    __shared__ int carry_s;
    int t = threadIdx.x, lane = t & 31, wid = t >> 5;
    if (t == 0) carry_s = 0;
    __syncthreads();
    for (int base = 0; base < n; base += 1024) {
        int i = base + t;
        int carry = carry_s;
        int v = (i < n) ? deg[i] : 0;
        int x = v;
#pragma unroll
        for (int o = 1; o < 32; o <<= 1) {
            int y = __shfl_up_sync(0xffffffffu, x, o);
            if (lane >= o) x += y;
        }
        if (lane == 31) wsum[wid] = x;
        __syncthreads();
        if (wid == 0) {
            int s = wsum[lane];
#pragma unroll
            for (int o = 1; o < 32; o <<= 1) {
                int y = __shfl_up_sync(0xffffffffu, s, o);
                if (lane >= o) s += y;
            }
            wsum[lane] = s;
        }
        __syncthreads();
        int woff = wid ? wsum[wid - 1] : 0;
        if (i < n) rowptr[i] = carry + woff + x - v;   // exclusive
        int total = wsum[31];
        __syncthreads();
        if (t == 0) carry_s = carry + total;
        __syncthreads();
    }
    if (t == 0) rowptr[n] = carry_s;
}

__global__ void k_scatter(const int* __restrict__ ei, const int* __restrict__ rowptr,
                          int* __restrict__ cursor, int* __restrict__ esrc,
                          int ne, int nn) {
    int i = blockIdx.x * blockDim.x + threadIdx.x;
    int tot = ne + nn;
    if (i >= tot) return;
    int s, d;
    if (i < ne) { s = ei[i]; d = ei[ne + i]; } else { s = d = i - ne; }
    int pos = rowptr[d] + atomicAdd(&cursor[d], 1);
    esrc[pos] = s;
}

// ---------------- fused GATv2 edge phase (flash-style online softmax) --------
// Layer 1: 4 heads x 128 ch. Writes agg1 as packed bf16 hi/lo words.
__global__ void k_fused1(const float* __restrict__ xl, const float* __restrict__ xr,
                         const int* __restrict__ rowptr, const int* __restrict__ esrc,
                         const float* __restrict__ att, const float* __restrict__ bias,
                         unsigned* __restrict__ aggq) {
    int node = blockIdx.x;
    int t = threadIdx.x, warp = t >> 5, lane = t & 31;
    int beg = rowptr[node], end = rowptr[node + 1];

    float xrv[16], attv[16];
    const float* pxr = xr + (size_t)node * 512;
#pragma unroll
    for (int i = 0; i < 16; i++) {
        int c = i * 32 + lane;
        xrv[i] = pxr[c];
        attv[i] = att[c];
    }
    float m[4] = {-INFINITY, -INFINITY, -INFINITY, -INFINITY};
    float s[4] = {0.f, 0.f, 0.f, 0.f};
    float acc[16] = {};

    for (int j = beg + warp; j < end; j += 4) {
        const float* px = xl + (size_t)esrc[j] * 512;
        float xv[16], p[4] = {0.f, 0.f, 0.f, 0.f};
#pragma unroll
        for (int i = 0; i < 16; i++) {
            xv[i] = px[i * 32 + lane];
            float v = xv[i] + xrv[i];
            v = v > 0.f ? v : 0.2f * v;
            p[i >> 2] += v * attv[i];
        }
#pragma unroll
        for (int o = 16; o; o >>= 1) {
            p[0] += __shfl_xor_sync(0xffffffffu, p[0], o);
            p[1] += __shfl_xor_sync(0xffffffffu, p[1], o);
            p[2] += __shfl_xor_sync(0xffffffffu, p[2], o);
            p[3] += __shfl_xor_sync(0xffffffffu, p[3], o);
        }
#pragma unroll
        for (int h = 0; h < 4; h++) {
            float e = p[h];
            float mn = fmaxf(m[h], e);
            float sc = __expf(m[h] - mn);       // first edge: exp(-inf)=0
            float w  = __expf(e - mn);
            s[h] = s[h] * sc + w;
            m[h] = mn;
#pragma unroll
            for (int i = 0; i < 4; i++) {
                int ii = h * 4 + i;
                acc[ii] = acc[ii] * sc + w * xv[ii];
            }
        }
    }

    __shared__ float sm[4][4], ss[4][4];
    __shared__ float sacc[4][512];
    if (lane < 4) { sm[warp][lane] = m[lane]; ss[warp][lane] = s[lane]; }
#pragma unroll
    for (int i = 0; i < 16; i++) sacc[warp][i * 32 + lane] = acc[i];
    __syncthreads();

#pragma unroll
    for (int h = 0; h < 4; h++) {
        int c = h * 128 + t;
        float M = fmaxf(fmaxf(sm[0][h], sm[1][h]), fmaxf(sm[2][h], sm[3][h]));
        float S = 0.f, A = 0.f;
#pragma unroll
        for (int w = 0; w < 4; w++) {
            float sc = __expf(sm[w][h] - M);    // empty warp: m=-inf -> 0
            S += ss[w][h] * sc;
            A += sacc[w][c] * sc;
        }
        float o_c = fmaxf(A / (S + 1e-16f) + bias[c], 0.f);
        float nb = __shfl_down_sync(0xffffffffu, o_c, 1);
        if (!(t & 1)) {
            unsigned hw, lw;
            split_pack(o_c, nb, hw, lw);
            int w = c >> 1;                     // = h*64 + t/2
            aggq[(size_t)node * 256 + w] = hw;
            aggq[(size_t)NN * 256 + (size_t)node * 256 + w] = lw;
        }
    }
}

// Layer 2 (1 head x 128 ch) + fused output head: out[node,10].
__global__ void k_fused2(const float* __restrict__ xl, const float* __restrict__ xr,
                         const int* __restrict__ rowptr, const int* __restrict__ esrc,
                         const float* __restrict__ att, const float* __restrict__ bias,
                         const float* __restrict__ oW, const float* __restrict__ ob,
                         float* __restrict__ out) {
    int node = blockIdx.x;
    int t = threadIdx.x, warp = t >> 5, lane = t & 31;
    int beg = rowptr[node], end = rowptr[node + 1];

    float xrv[4], attv[4];
    const float* pxr = xr + (size_t)node * 128;
#pragma unroll
    for (int i = 0; i < 4; i++) {
        int c = i * 32 + lane;
        xrv[i] = pxr[c];
        attv[i] = att[c];
    }
    float m = -INFINITY, s = 0.f;
    float acc[4] = {};

    for (int j = beg + warp; j < end; j += 4) {
        const float* px = xl + (size_t)esrc[j] * 128;
        float xv[4], p = 0.f;
#pragma unroll
        for (int i = 0; i < 4; i++) {
            xv[i] = px[i * 32 + lane];
            float v = xv[i] + xrv[i];
            v = v > 0.f ? v : 0.2f * v;
            p += v * attv[i];
        }
#pragma unroll
        for (int o = 16; o; o >>= 1) p += __shfl_xor_sync(0xffffffffu, p, o);
        float mn = fmaxf(m, p);
        float sc = __expf(m - mn);
        float w  = __expf(p - mn);
        s = s * sc + w;
        m = mn;
#pragma unroll
        for (int i = 0; i < 4; i++) acc[i] = acc[i] * sc + w * xv[i];
    }

    __shared__ float sm[4], ss[4];
    __shared__ float sacc[4][128];
    if (!lane) { sm[warp] = m; ss[warp] = s; }
#pragma unroll
    for (int i = 0; i < 4; i++) sacc[warp][i * 32 + lane] = acc[i];
    __syncthreads();

    float M = fmaxf(fmaxf(sm[0], sm[1]), fmaxf(sm[2], sm[3]));
    float S = 0.f, A = 0.f;
#pragma unroll
    for (int w = 0; w < 4; w++) {
        float sc = __expf(sm[w] - M);
        S += ss[w] * sc;
        A += sacc[w][t] * sc;
    }
    float o_t = A / (S + 1e-16f) + bias[t];   // hidden value, channel t

    // fused output head: out[node,o] = sum_t o_t * oW[t,o] + ob[o]
    float p[10];
#pragma unroll
    for (int o = 0; o < 10; o++) p[o] = o_t * oW[t * 10 + o];
#pragma unroll
    for (int off = 16; off; off >>= 1)
#pragma unroll
        for (int o = 0; o < 10; o++) p[o] += __shfl_xor_sync(0xffffffffu, p[o], off);
    __shared__ float pp[4][10];
    if (!lane)
#pragma unroll
        for (int o = 0; o < 10; o++) pp[warp][o] = p[o];
    __syncthreads();
    if (t < 10) {
        float v = ob[t];
#pragma unroll
        for (int w = 0; w < 4; w++) v += pp[w][t];
        out[(size_t)node * 10 + t] = v;
    }
}

// ---------------- launch ----------------------------------------------------
extern "C" void kernel_launch(void* const* d_in, const int* in_sizes, int n_in,
                              void* d_out, int out_size) {
    const float* xp   = (const float*)d_in[0];
    const int*   ei   = (const int*)  d_in[1];
    const float* emb  = (const float*)d_in[2];
    const float* pW   = (const float*)d_in[3];
    const float* pb   = (const float*)d_in[4];
    const float* W1l  = (const float*)d_in[5];
    const float* W1r  = (const float*)d_in[6];
    const float* att1 = (const float*)d_in[7];
    const float* b1   = (const float*)d_in[8];
    const float* W2l  = (const float*)d_in[9];
    const float* W2r  = (const float*)d_in[10];
    const float* att2 = (const float*)d_in[11];
    const float* b2   = (const float*)d_in[12];
    const float* oW   = (const float*)d_in[13];
    const float* ob   = (const float*)d_in[14];
    float* out = (float*)d_out;

    int n  = in_sizes[0] / 65;
    int ne = in_sizes[1] / 2;
    int et = ne + n;

    unsigned *combq, *x0q, *agg1q, *pWq, *W1lq, *W1rq, *W2lq, *W2rq;
    float *xl1, *xr1, *xl2, *xr2;
    int *deg, *cursor, *rowptr, *esrc;
    cudaGetSymbolAddress((void**)&combq, g_combq);
    cudaGetSymbolAddress((void**)&x0q,   g_x0q);
    cudaGetSymbolAddress((void**)&agg1q, g_agg1q);
    cudaGetSymbolAddress((void**)&pWq,   g_pWq);
    cudaGetSymbolAddress((void**)&W1lq,  g_W1lq);
    cudaGetSymbolAddress((void**)&W1rq,  g_W1rq);
    cudaGetSymbolAddress((void**)&W2lq,  g_W2lq);
    cudaGetSymbolAddress((void**)&W2rq,  g_W2rq);
    cudaGetSymbolAddress((void**)&xl1,   g_xl1);
    cudaGetSymbolAddress((void**)&xr1,   g_xr1);
    cudaGetSymbolAddress((void**)&xl2,   g_xl2);
    cudaGetSymbolAddress((void**)&xr2,   g_xr2);
    cudaGetSymbolAddress((void**)&deg,    g_deg);
    cudaGetSymbolAddress((void**)&cursor, g_cursor);
    cudaGetSymbolAddress((void**)&rowptr, g_rowptr);
    cudaGetSymbolAddress((void**)&esrc,   g_esrc);

    const int TB = 256;
    int gm = (n + 63) / 64;

    // ---- CSR build ----
    cudaMemsetAsync(deg, 0, (size_t)(n + 1) * sizeof(int));
    cudaMemsetAsync(cursor, 0, (size_t)n * sizeof(int));
    k_hist<<<(et + TB - 1) / TB, TB>>>(ei, deg, ne, n);
    k_scan<<<1, 1024>>>(deg, rowptr, n);
    k_scatter<<<(et + TB - 1) / TB, TB>>>(ei, rowptr, cursor, esrc, ne, n);

    // ---- pre-split weights + combined features ----
    k_wsplit<<<(96 * 128 + TB - 1) / TB, TB>>>(pW,  pWq,  96, 128);
    k_wsplit<<<(64 * 512 + TB - 1) / TB, TB>>>(W1l, W1lq, 64, 512);
    k_wsplit<<<(64 * 512 + TB - 1) / TB, TB>>>(W1r, W1rq, 64, 512);
    k_wsplit<<<(256 * 128 + TB - 1) / TB, TB>>>(W2l, W2lq, 256, 128);
    k_wsplit<<<(256 * 128 + TB - 1) / TB, TB>>>(W2r, W2rq, 256, 128);
    k_combsplit<<<(n * 96 + TB - 1) / TB, TB>>>(xp, emb, combq, n);

    // ---- proj -> x0 (split output) ----
    k_gemm<true><<<dim3(1, gm), TB, GEMM_SMEM>>>(
        combq, NN * 96, 96, pWq, nullptr, 96 * 128, pb,
        nullptr, nullptr, x0q, n * 64, n, 128, 192, 1, 1);

    // ---- layer 1: xl1 | xr1 in one launch ----
    k_gemm<false><<<dim3(8, gm), TB, GEMM_SMEM>>>(
        x0q, NN * 64, 64, W1lq, W1rq, 64 * 512, nullptr,
        xl1, xr1, nullptr, 0, n, 512, 128, 0, 4);
    k_fused1<<<n, 128>>>(xl1, xr1, rowptr, esrc, att1, b1, agg1q);

    // ---- layer 2: xl2 | xr2 in one launch ----
    k_gemm<false><<<dim3(2, gm), TB, GEMM_SMEM>>>(
        agg1q, NN * 256, 256, W2lq, W2rq, 256 * 128, nullptr,
        xl2, xr2, nullptr, 0, n, 128, 512, 0, 1);
    k_fused2<<<n, 128>>>(xl2, xr2, rowptr, esrc, att2, b2, oW, ob, out);
}